// round 8
// baseline (speedup 1.0000x reference)
#include <cuda_runtime.h>
#include <cuda_bf16.h>
#include <stdint.h>

#define CCH 128
#define THREADS 256
#define GRIDP 148

// ---- device scratch ----
__device__ float    g_bias[32 * CCH];
__device__ float    g_tco[CCH];            // t_o / 32512 (dequant step of W row o)
__device__ uint32_t g_Wq[2][CCH][64];      // [hi/lo][o][k/4] packed s8 of Wcat/t_o
__device__ float    g_bufA[262144 * 128];
__device__ float    g_bufB[131072 * 128];
__device__ int      g_barCount;
__device__ volatile unsigned g_barGen;

// ---- SMEM layout (bytes) ----
// X: [buf][plane hi/lo] 64 rows x 256B (k = 256 int8: tap0 0-127, tap1 128-255)
#define XBUF(b, s) ((b) * 32768 + (s) * 16384)
#define SM_WH   65536              // W hi: 128 rows x 256B
#define SM_WL   98304              // W lo
#define SM_STAGE 131072            // 32 rows x 136 floats
#define SM_RMAX  148480            // [buf][68] floats (row maxima)
#define SM_SINV  149056            // [buf][64] floats (per-output-row dequant step)
#define SM_TOT   149568
#define STAGE_STRIDE 136

__device__ __forceinline__ uint32_t smem_u32(const void* p) {
    uint32_t a;
    asm("{ .reg .u64 t; cvta.to.shared.u64 t, %1; cvt.u32.u64 %0, t; }" : "=r"(a) : "l"(p));
    return a;
}
__device__ __forceinline__ void ldx4(uint32_t& r0, uint32_t& r1, uint32_t& r2, uint32_t& r3,
                                     uint32_t addr) {
    asm volatile("ldmatrix.sync.aligned.m8n8.x4.shared.b16 {%0,%1,%2,%3}, [%4];"
                 : "=r"(r0), "=r"(r1), "=r"(r2), "=r"(r3) : "r"(addr));
}
__device__ __forceinline__ void mma_s8(int* d, const uint32_t* a, const uint32_t* b) {
    asm volatile("mma.sync.aligned.m16n8k32.row.col.s32.s8.s8.s32 "
                 "{%0,%1,%2,%3}, {%4,%5,%6,%7}, {%8,%9}, {%0,%1,%2,%3};"
                 : "+r"(d[0]), "+r"(d[1]), "+r"(d[2]), "+r"(d[3])
                 : "r"(a[0]), "r"(a[1]), "r"(a[2]), "r"(a[3]), "r"(b[0]), "r"(b[1]));
}
#define STS64(addr, x, y) \
    asm volatile("st.shared.v2.u32 [%0], {%1,%2};" :: "r"(addr), "r"(x), "r"(y) : "memory")
#define STS32(addr, x) \
    asm volatile("st.shared.u32 [%0], %1;" :: "r"(addr), "r"(x) : "memory")

// quantize float4 by rq into int16, split to (hi s8 pack, lo s8 pack)
__device__ __forceinline__ void quant_pack(float4 v, float rq, uint32_t& ph, uint32_t& pl) {
    int q0 = __float2int_rn(v.x * rq), q1 = __float2int_rn(v.y * rq);
    int q2 = __float2int_rn(v.z * rq), q3 = __float2int_rn(v.w * rq);
    int h0 = (q0 + 128) >> 8, h1 = (q1 + 128) >> 8;
    int h2 = (q2 + 128) >> 8, h3 = (q3 + 128) >> 8;
    int l0 = q0 - (h0 << 8), l1 = q1 - (h1 << 8);
    int l2 = q2 - (h2 << 8), l3 = q3 - (h3 << 8);
    ph = (h0 & 255) | ((h1 & 255) << 8) | ((h2 & 255) << 16) | ((h3 & 255) << 24);
    pl = (l0 & 255) | ((l1 & 255) << 8) | ((l2 & 255) << 16) | ((l3 & 255) << 24);
}

// sense-reversing grid barrier; safe: all GRIDP CTAs co-resident (1 CTA/SM).
__device__ __forceinline__ void grid_barrier() {
    __syncthreads();
    if (threadIdx.x == 0) {
        unsigned gen = g_barGen;
        __threadfence();
        if (atomicAdd(&g_barCount, 1) == (int)gridDim.x - 1) {
            g_barCount = 0;
            __threadfence();
            g_barGen = gen + 1;
        } else {
            while (g_barGen == gen) { }
        }
        __threadfence();
    }
    __syncthreads();
}

// ---------------------------------------------------------------------------
__global__ void precompute_kernel(const float* __restrict__ W,
                                  const float* __restrict__ b,
                                  const float* __restrict__ depth,
                                  int nlev) {
    int tid = threadIdx.x;
    if (tid < CCH) {
        int o = tid;
        // quantize Wcat row o (k<128 -> tap0, k>=128 -> tap1)
        float t = 0.f;
        for (int k = 0; k < 256; ++k) {
            float w = (k < 128) ? W[(size_t)o * 512 + k * 2]
                                : W[(size_t)o * 512 + (k - 128) * 2 + 1];
            t = fmaxf(t, fabsf(w));
        }
        g_tco[o] = t * (1.f / 32512.f);
        float rw = 32512.f / fmaxf(t, 1e-30f);
        for (int k4 = 0; k4 < 64; ++k4) {
            uint32_t ph = 0, pl = 0;
            #pragma unroll
            for (int j = 0; j < 4; ++j) {
                int k = k4 * 4 + j;
                float w = (k < 128) ? W[(size_t)o * 512 + k * 2]
                                    : W[(size_t)o * 512 + (k - 128) * 2 + 1];
                int q = __float2int_rn(w * rw);
                int h = (q + 128) >> 8, lo = q - (h << 8);
                ph |= (uint32_t)(h & 255) << (8 * j);
                pl |= (uint32_t)(lo & 255) << (8 * j);
            }
            g_Wq[0][o][k4] = ph;
            g_Wq[1][o][k4] = pl;
        }
        // per-level effective bias (depth channels folded, exact fp32)
        float ws[CCH];
        #pragma unroll 4
        for (int c = 0; c < CCH; ++c)
            ws[c] = W[(size_t)o * 512 + (128 + c) * 2 + 0] +
                    W[(size_t)o * 512 + (128 + c) * 2 + 1];
        for (int lev = 0; lev < nlev; ++lev) {
            float s = b[o];
            #pragma unroll 4
            for (int c = 0; c < CCH; ++c) s += ws[c] * depth[lev * CCH + c];
            g_bias[lev * CCH + o] = s;
        }
    }
}

// ---------------------------------------------------------------------------
// Persistent int8-IMMA kernel. Per tile (64 conv positions x 128 o):
// D = Xq[64, K=256] * Wq[128, 256]^T with int16 = 256*hi + lo split,
// 3 products (hh, h*l, l*h), per-output-row dynamic scales.
// ---------------------------------------------------------------------------
__global__ __launch_bounds__(THREADS)
void persistent_kernel(const float* __restrict__ Xin, const int* __restrict__ perm,
                       float* bufA, float* bufB, float* outp, int N) {
    extern __shared__ char smem[];
    const uint32_t sb = smem_u32(smem);
    float* stagef = (float*)(smem + SM_STAGE);
    float* rmaxA  = (float*)(smem + SM_RMAX);    // [buf*68 + row]
    float* sinvA  = (float*)(smem + SM_SINV);    // [buf*64 + row]
    const int tid = threadIdx.x, l = tid & 31, wid = tid >> 5;
    const int wm = (wid >> 2) * 32, wn = (wid & 3) * 32;
    const int bid = blockIdx.x;

    // ---- W planes -> smem once ----
    for (int i = tid; i < 2 * 128 * 32; i += THREADS) {
        int plane = i >> 12, rem = i & 4095, o = rem >> 5, u = rem & 31;
        uint2 v = ((const uint2*)&g_Wq[plane][o][0])[u];
        uint32_t byte = (uint32_t)o * 256 + (((uint32_t)u * 8) ^ (uint32_t)((o & 7) << 4));
        STS64(sb + (plane ? SM_WL : SM_WH) + byte, v.x, v.y);
    }

    // ---- per-lane fragment address constants ----
    const int arl = ((l >> 3) & 1) * 8 + (l & 7);
    uint32_t aAddr[2], aS[2];
    #pragma unroll
    for (int mt = 0; mt < 2; ++mt) {
        int row = wm + mt * 16 + arl;
        aAddr[mt] = (uint32_t)row * 256;
        aS[mt] = (uint32_t)((row & 7) << 4);
    }
    uint32_t bRow[2], bS[2];
    #pragma unroll
    for (int g = 0; g < 2; ++g) {
        int o = wn + g * 16 + ((l >> 4) & 1) * 8 + (l & 7);
        bRow[g] = (uint32_t)o * 256;
        bS[g] = (uint32_t)((o & 7) << 4);
    }
    const uint32_t a_k8b = ((l >> 4) & 1) * 16;
    const uint32_t b_k8b = ((l >> 3) & 1) * 16;
    // loader: thread (wid,l) owns rows wid+8*s9, cols 4l..4l+3
    const uint32_t sw0 = ((uint32_t)wid << 4);          // row&7 == wid
    const uint32_t sw1 = ((uint32_t)((wid + 7) & 7) << 4);
    const uint32_t cb0 = (uint32_t)l * 4;
    const uint32_t cb1 = 128u + (uint32_t)l * 4;

    // per-o dequant steps (constant for all levels)
    float tcx[4], tcy[4];
    #pragma unroll
    for (int nt = 0; nt < 4; ++nt) {
        int o0 = wn + nt * 8 + (l & 3) * 2;
        tcx[nt] = g_tco[o0];
        tcy[nt] = g_tco[o0 + 1];
    }

    const float* Xcur = Xin;
    int L = N;

    for (int lvl = 0; L > 1; ++lvl) {
        const int Lout = (L - 1) >> 1;
        float* Yout = (Lout == 1) ? outp : ((lvl & 1) ? bufB : bufA);
        const int* pm = (lvl == 0) ? perm : nullptr;
        const int ntiles = (Lout + 31) >> 5;

        float bx[4], by[4];
        #pragma unroll
        for (int nt = 0; nt < 4; ++nt) {
            float2 bb = *(const float2*)&g_bias[lvl * CCH + wn + nt * 8 + (l & 3) * 2];
            bx[nt] = bb.x; by[nt] = bb.y;
        }

        // ---- prologue: load + quantize first tile into buf 0 ----
        int cur = 0;
        if (bid < ntiles) {
            const int pbase = bid << 6;
            float4 v[9];
            #pragma unroll
            for (int s9 = 0; s9 < 9; ++s9) {
                if (s9 == 8 && wid != 0) break;
                int row = s9 * 8 + wid;
                int pin = pbase + row; if (pin > L - 1) pin = L - 1;
                size_t srow = pm ? (size_t)pm[pin] : (size_t)pin;
                v[s9] = *((const float4*)(Xcur + srow * CCH) + l);
                float m = fmaxf(fmaxf(fabsf(v[s9].x), fabsf(v[s9].y)),
                                fmaxf(fabsf(v[s9].z), fabsf(v[s9].w)));
                #pragma unroll
                for (int d = 16; d > 0; d >>= 1)
                    m = fmaxf(m, __shfl_xor_sync(0xffffffffu, m, d));
                if (l == 0) rmaxA[row] = m;
            }
            __syncthreads();
            #pragma unroll
            for (int s9 = 0; s9 < 9; ++s9) {
                if (s9 == 8 && wid != 0) break;
                int row = s9 * 8 + wid;
                if (row < 64) {
                    float mm = fmaxf(fmaxf(rmaxA[row], rmaxA[row + 1]), 1e-30f);
                    uint32_t ph, pl2;
                    quant_pack(v[s9], 32512.f / mm, ph, pl2);
                    uint32_t a = (uint32_t)row * 256 + (cb0 ^ sw0);
                    STS32(sb + XBUF(0, 0) + a, ph);
                    STS32(sb + XBUF(0, 1) + a, pl2);
                    if (l == 0) sinvA[row] = fmaxf(rmaxA[row], rmaxA[row + 1]) * (1.f / 32512.f);
                }
                if (row >= 1) {
                    float mm = fmaxf(fmaxf(rmaxA[row - 1], rmaxA[row]), 1e-30f);
                    uint32_t ph, pl2;
                    quant_pack(v[s9], 32512.f / mm, ph, pl2);
                    uint32_t a = (uint32_t)(row - 1) * 256 + (cb1 ^ sw1);
                    STS32(sb + XBUF(0, 0) + a, ph);
                    STS32(sb + XBUF(0, 1) + a, pl2);
                }
            }
        }
        __syncthreads();

        for (int tile = bid; tile < ntiles; tile += GRIDP) {
            const int nexttile = tile + GRIDP;
            const bool hasnext = nexttile < ntiles;
            const int nb = cur ^ 1;

            // ---- 1. prefetch next tile's X into registers ----
            float4 pr[9];
            if (hasnext) {
                const int pbase = nexttile << 6;
                #pragma unroll
                for (int s9 = 0; s9 < 9; ++s9) {
                    if (s9 == 8 && wid != 0) break;
                    int row = s9 * 8 + wid;
                    int pin = pbase + row; if (pin > L - 1) pin = L - 1;
                    size_t srow = pm ? (size_t)pm[pin] : (size_t)pin;
                    pr[s9] = *((const float4*)(Xcur + srow * CCH) + l);
                }
            }

            // ---- 2. IMMA from buf[cur] ----
            int acch[2][4][4], accm[2][4][4];
            #pragma unroll
            for (int mt = 0; mt < 2; ++mt)
                #pragma unroll
                for (int nt = 0; nt < 4; ++nt)
                    #pragma unroll
                    for (int r = 0; r < 4; ++r) { acch[mt][nt][r] = 0; accm[mt][nt][r] = 0; }

            const uint32_t xh = sb + XBUF(cur, 0);
            const uint32_t xl = sb + XBUF(cur, 1);
            #pragma unroll
            for (int kt = 0; kt < 8; ++kt) {
                const uint32_t chA = (uint32_t)kt * 32 + a_k8b;
                const uint32_t chB = (uint32_t)kt * 32 + b_k8b;

                uint32_t Bh[4][2], Bl[4][2];
                ldx4(Bh[0][0], Bh[0][1], Bh[1][0], Bh[1][1], sb + SM_WH + bRow[0] + (chB ^ bS[0]));
                ldx4(Bh[2][0], Bh[2][1], Bh[3][0], Bh[3][1], sb + SM_WH + bRow[1] + (chB ^ bS[1]));
                ldx4(Bl[0][0], Bl[0][1], Bl[1][0], Bl[1][1], sb + SM_WL + bRow[0] + (chB ^ bS[0]));
                ldx4(Bl[2][0], Bl[2][1], Bl[3][0], Bl[3][1], sb + SM_WL + bRow[1] + (chB ^ bS[1]));

                #pragma unroll
                for (int mt = 0; mt < 2; ++mt) {
                    const uint32_t aoff = aAddr[mt] + (chA ^ aS[mt]);
                    uint32_t Ah[4], Al[4];
                    ldx4(Ah[0], Ah[1], Ah[2], Ah[3], xh + aoff);
                    ldx4(Al[0], Al[1], Al[2], Al[3], xl + aoff);
                    #pragma unroll
                    for (int nt = 0; nt < 4; ++nt) {
                        mma_s8(acch[mt][nt], Ah, Bh[nt]);
                        mma_s8(accm[mt][nt], Ah, Bl[nt]);
                        mma_s8(accm[mt][nt], Al, Bh[nt]);
                    }
                }
            }

            // ---- 3. row maxima of prefetched tile ----
            if (hasnext) {
                #pragma unroll
                for (int s9 = 0; s9 < 9; ++s9) {
                    if (s9 == 8 && wid != 0) break;
                    float m = fmaxf(fmaxf(fabsf(pr[s9].x), fabsf(pr[s9].y)),
                                    fmaxf(fabsf(pr[s9].z), fabsf(pr[s9].w)));
                    #pragma unroll
                    for (int d = 16; d > 0; d >>= 1)
                        m = fmaxf(m, __shfl_xor_sync(0xffffffffu, m, d));
                    if (l == 0) rmaxA[nb * 68 + s9 * 8 + wid] = m;
                }
            }

            // ---- 4. epilogue: dequant + bias + leaky + pool -> stage ----
            const int r2 = l >> 2;
            const bool storer = ((r2 & 1) == 0);
            const float* sinvC = sinvA + cur * 64;
            #pragma unroll
            for (int mt = 0; mt < 2; ++mt) {
                const float sp0 = sinvC[wm + mt * 16 + r2];
                const float sp1 = sinvC[wm + mt * 16 + r2 + 8];
                #pragma unroll
                for (int nt = 0; nt < 4; ++nt) {
                    float f0 = (float)acch[mt][nt][0] * 65536.f + (float)accm[mt][nt][0] * 256.f;
                    float f1 = (float)acch[mt][nt][1] * 65536.f + (float)accm[mt][nt][1] * 256.f;
                    float f2 = (float)acch[mt][nt][2] * 65536.f + (float)accm[mt][nt][2] * 256.f;
                    float f3 = (float)acch[mt][nt][3] * 65536.f + (float)accm[mt][nt][3] * 256.f;
                    float v0 = f0 * (sp0 * tcx[nt]) + bx[nt];
                    float v1 = f1 * (sp0 * tcy[nt]) + by[nt];
                    float v2 = f2 * (sp1 * tcx[nt]) + bx[nt];
                    float v3 = f3 * (sp1 * tcy[nt]) + by[nt];
                    v0 = v0 >= 0.f ? v0 : 0.2f * v0;
                    v1 = v1 >= 0.f ? v1 : 0.2f * v1;
                    v2 = v2 >= 0.f ? v2 : 0.2f * v2;
                    v3 = v3 >= 0.f ? v3 : 0.2f * v3;
                    float u0 = fmaxf(v0, __shfl_xor_sync(0xffffffffu, v0, 4));
                    float u1 = fmaxf(v1, __shfl_xor_sync(0xffffffffu, v1, 4));
                    float u2 = fmaxf(v2, __shfl_xor_sync(0xffffffffu, v2, 4));
                    float u3 = fmaxf(v3, __shfl_xor_sync(0xffffffffu, v3, 4));
                    if (storer) {
                        const int o0 = wn + nt * 8 + (l & 3) * 2;
                        const int jl = (wm + mt * 16 + r2) >> 1;   // 0..31
                        *(float2*)&stagef[jl * STAGE_STRIDE + o0] = make_float2(u0, u1);
                        *(float2*)&stagef[(jl + 4) * STAGE_STRIDE + o0] = make_float2(u2, u3);
                    }
                }
            }
            __syncthreads();   // SYNC1: rmax + stage visible; MMA reads of buf done

            // ---- 5. quantize prefetched tile into buf[nb] ----
            if (hasnext) {
                const float* rm = rmaxA + nb * 68;
                #pragma unroll
                for (int s9 = 0; s9 < 9; ++s9) {
                    if (s9 == 8 && wid != 0) break;
                    int row = s9 * 8 + wid;
                    if (row < 64) {
                        float mm = fmaxf(fmaxf(rm[row], rm[row + 1]), 1e-30f);
                        uint32_t ph, pl2;
                        quant_pack(pr[s9], 32512.f / mm, ph, pl2);
                        uint32_t a = (uint32_t)row * 256 + (cb0 ^ sw0);
                        STS32(sb + XBUF(nb, 0) + a, ph);
                        STS32(sb + XBUF(nb, 1) + a, pl2);
                        if (l == 0)
                            sinvA[nb * 64 + row] = fmaxf(rm[row], rm[row + 1]) * (1.f / 32512.f);
                    }
                    if (row >= 1) {
                        float mm = fmaxf(fmaxf(rm[row - 1], rm[row]), 1e-30f);
                        uint32_t ph, pl2;
                        quant_pack(pr[s9], 32512.f / mm, ph, pl2);
                        uint32_t a = (uint32_t)(row - 1) * 256 + (cb1 ^ sw1);
                        STS32(sb + XBUF(nb, 0) + a, ph);
                        STS32(sb + XBUF(nb, 1) + a, pl2);
                    }
                }
            }

            // ---- 6. coalesced store: 32 rows x 128 floats ----
            const int jbase = tile << 5;
            #pragma unroll
            for (int k = 0; k < 4; ++k) {
                int idx = tid + k * THREADS;
                int row = idx >> 5, c4 = idx & 31;
                if (jbase + row < Lout) {
                    float4 v = *(const float4*)&stagef[row * STAGE_STRIDE + c4 * 4];
                    *(float4*)&Yout[(size_t)(jbase + row) * CCH + c4 * 4] = v;
                }
            }
            __syncthreads();   // SYNC2: X buf[nb] + sinv ready; stage free
            cur ^= 1;
        }

        grid_barrier();
        Xcur = Yout;
        L = Lout;
    }
}

// ---------------------------------------------------------------------------
extern "C" void kernel_launch(void* const* d_in, const int* in_sizes, int n_in,
                              void* d_out, int out_size) {
    const float* x     = (const float*)d_in[0];
    const float* depth = (const float*)d_in[1];
    const float* W     = (const float*)d_in[2];
    const float* b     = (const float*)d_in[3];
    const int*   perm  = (const int*)d_in[4];
    float* out = (float*)d_out;

    int N = in_sizes[0] / CCH;
    int nlev = 0;
    { int L = N; while (L > 1) { L = (L - 1) / 2; nlev++; } }

    cudaFuncSetAttribute((const void*)persistent_kernel,
                         cudaFuncAttributeMaxDynamicSharedMemorySize, SM_TOT);

    precompute_kernel<<<1, 256>>>(W, b, depth, nlev);

    float *bufA, *bufB;
    cudaGetSymbolAddress((void**)&bufA, g_bufA);
    cudaGetSymbolAddress((void**)&bufB, g_bufB);

    persistent_kernel<<<GRIDP, THREADS, SM_TOT>>>(x, perm, bufA, bufB, out, N);
}

// round 9
// speedup vs baseline: 2.5034x; 2.5034x over previous
#include <cuda_runtime.h>
#include <cuda_bf16.h>
#include <stdint.h>

#define CCH 128
#define THREADS 256
#define GRIDP 148

// ---- device scratch ----
__device__ float    g_bias[32 * CCH];
__device__ uint32_t g_Wtm[2][CCH][128];     // [hi/lo][o][k/2] bf16x2 of Acat=[W0 W1]
// bf16 plane buffers (uint32 = 2 ch)
__device__ uint32_t g_Ah[262144 * 64], g_Al[262144 * 64];   // even-level out
__device__ uint32_t g_Bh[131072 * 64], g_Bl[131072 * 64];   // odd-level out
__device__ int      g_barCount;
__device__ volatile unsigned g_barGen;

// ---- SMEM layout (bytes) ----
// X region 67072B:
//   levels>=1: XH1 @0 (129 rows x 256B = 33024), XL1 @33536
//   level 0  : X0BUF(b,s) = s*33536 + b*16768 (65 rows x 256B each)
#define XH1 0
#define XL1 33536
#define X0BUF(b, s) ((s) * 33536 + (b) * 16768)
#define SM_WH   67072
#define SM_WL   (67072 + 65536)
#define SM_STAGE 198144            // 2 planes x 32 rows x 272B = 17408
#define SM_TOT   215552
#define STG_ROW 272                // stage row stride (bytes)

__device__ __forceinline__ uint32_t smem_u32(const void* p) {
    uint32_t a;
    asm("{ .reg .u64 t; cvta.to.shared.u64 t, %1; cvt.u32.u64 %0, t; }" : "=r"(a) : "l"(p));
    return a;
}
__device__ __forceinline__ void ldx4(uint32_t& r0, uint32_t& r1, uint32_t& r2, uint32_t& r3,
                                     uint32_t addr) {
    asm volatile("ldmatrix.sync.aligned.m8n8.x4.shared.b16 {%0,%1,%2,%3}, [%4];"
                 : "=r"(r0), "=r"(r1), "=r"(r2), "=r"(r3) : "r"(addr));
}
__device__ __forceinline__ void mma_bf16(float* d, const uint32_t* a, const uint32_t* b) {
    asm volatile("mma.sync.aligned.m16n8k16.row.col.f32.bf16.bf16.f32 "
                 "{%0,%1,%2,%3}, {%4,%5,%6,%7}, {%8,%9}, {%0,%1,%2,%3};"
                 : "+f"(d[0]), "+f"(d[1]), "+f"(d[2]), "+f"(d[3])
                 : "r"(a[0]), "r"(a[1]), "r"(a[2]), "r"(a[3]), "r"(b[0]), "r"(b[1]));
}
#define STS64(addr, x, y) \
    asm volatile("st.shared.v2.u32 [%0], {%1,%2};" :: "r"(addr), "r"(x), "r"(y) : "memory")
#define STS32(addr, x) \
    asm volatile("st.shared.u32 [%0], %1;" :: "r"(addr), "r"(x) : "memory")
#define CP_ASYNC16(dst, src) \
    asm volatile("cp.async.cg.shared.global [%0], [%1], 16;" :: "r"(dst), "l"(src) : "memory")
#define CP_COMMIT() asm volatile("cp.async.commit_group;" ::: "memory")
#define CP_WAIT0()  asm volatile("cp.async.wait_group 0;" ::: "memory")

__device__ __forceinline__ void cvt_sts(float4 v, uint32_t dstH, uint32_t dstL) {
    __nv_bfloat16 h0 = __float2bfloat16_rn(v.x), h1 = __float2bfloat16_rn(v.y);
    __nv_bfloat16 h2 = __float2bfloat16_rn(v.z), h3 = __float2bfloat16_rn(v.w);
    __nv_bfloat16 l0 = __float2bfloat16_rn(v.x - __bfloat162float(h0));
    __nv_bfloat16 l1 = __float2bfloat16_rn(v.y - __bfloat162float(h1));
    __nv_bfloat16 l2 = __float2bfloat16_rn(v.z - __bfloat162float(h2));
    __nv_bfloat16 l3 = __float2bfloat16_rn(v.w - __bfloat162float(h3));
    __nv_bfloat162 hp0 = {h0, h1}, hp1 = {h2, h3};
    __nv_bfloat162 lp0 = {l0, l1}, lp1 = {l2, l3};
    STS64(dstH, *(uint32_t*)&hp0, *(uint32_t*)&hp1);
    STS64(dstL, *(uint32_t*)&lp0, *(uint32_t*)&lp1);
}
// pack two floats into bf16x2 hi pack + residual lo pack
__device__ __forceinline__ void pack_hl(float a, float b, uint32_t& hp, uint32_t& lp) {
    __nv_bfloat16 ha = __float2bfloat16_rn(a), hb = __float2bfloat16_rn(b);
    __nv_bfloat16 la = __float2bfloat16_rn(a - __bfloat162float(ha));
    __nv_bfloat16 lb = __float2bfloat16_rn(b - __bfloat162float(hb));
    __nv_bfloat162 h = {ha, hb}, lo = {la, lb};
    hp = *(uint32_t*)&h; lp = *(uint32_t*)&lo;
}

__device__ __forceinline__ void grid_barrier() {
    __syncthreads();
    if (threadIdx.x == 0) {
        unsigned gen = g_barGen;
        __threadfence();
        if (atomicAdd(&g_barCount, 1) == (int)gridDim.x - 1) {
            g_barCount = 0;
            __threadfence();
            g_barGen = gen + 1;
        } else {
            while (g_barGen == gen) { }
        }
        __threadfence();
    }
    __syncthreads();
}

// ---------------------------------------------------------------------------
__global__ void precompute_kernel(const float* __restrict__ W,
                                  const float* __restrict__ b,
                                  const float* __restrict__ depth,
                                  int nlev) {
    int tid = threadIdx.x;
    for (int i = tid; i < 2 * CCH * 128; i += blockDim.x) {
        int s = i >> 14, o = (i >> 7) & 127, col = i & 127;
        uint32_t out = 0;
        #pragma unroll
        for (int h = 0; h < 2; ++h) {
            int c = 2 * col + h;
            float w = (c < 128) ? W[(size_t)o * 512 + c * 2]
                                : W[(size_t)o * 512 + (c - 128) * 2 + 1];
            __nv_bfloat16 hi = __float2bfloat16_rn(w);
            __nv_bfloat16 v = (s == 0) ? hi
                              : __float2bfloat16_rn(w - __bfloat162float(hi));
            uint16_t bits = *(uint16_t*)&v;
            out |= (uint32_t)bits << (16 * h);
        }
        g_Wtm[s][o][col] = out;
    }
    if (tid < CCH) {
        int o = tid;
        float ws[CCH];
        #pragma unroll 4
        for (int c = 0; c < CCH; ++c)
            ws[c] = W[(size_t)o * 512 + (128 + c) * 2 + 0] +
                    W[(size_t)o * 512 + (128 + c) * 2 + 1];
        for (int lev = 0; lev < nlev; ++lev) {
            float s = b[o];
            #pragma unroll 4
            for (int c = 0; c < CCH; ++c) s += ws[c] * depth[lev * CCH + c];
            g_bias[lev * CCH + o] = s;
        }
    }
}

// ---------------------------------------------------------------------------
// Persistent kernel.
// Level 0: R7 path — gather fp32 via perm, cvt->bf16 hi/lo, 64-pos tiles,
//          double-buffered, reg-prefetch pipelined.
// Levels >=1: cp.async bf16 planes -> smem, 128-pos tiles, single buffer.
// All levels output bf16 hi/lo planes; final level also writes fp32 out.
// ---------------------------------------------------------------------------
__global__ __launch_bounds__(THREADS)
void persistent_kernel(const float* __restrict__ Xin, const int* __restrict__ perm,
                       float* __restrict__ outp, int N) {
    extern __shared__ char smem[];
    const uint32_t sb = smem_u32(smem);
    char* stage = smem + SM_STAGE;
    const int tid = threadIdx.x, l = tid & 31, wid = tid >> 5;
    const int wn = (wid & 3) * 32;
    const int wm0 = (wid >> 2) * 32;     // level-0 path (64-pos tile)
    const int wmB = (wid >> 2) * 64;     // big path (128-pos tile)
    const int bid = blockIdx.x;

    // ---- W -> smem once ----
    for (int i = tid; i < 2 * 128 * 64; i += THREADS) {
        int split = i >> 13, rem = i & 8191, o = rem >> 6, u = rem & 63;
        uint2 v = ((const uint2*)&g_Wtm[split][o][0])[u];
        uint32_t byte = (uint32_t)o * 512 + (((uint32_t)u * 8) ^ (uint32_t)((o & 7) << 4));
        STS64(sb + (split ? SM_WL : SM_WH) + byte, v.x, v.y);
    }

    // ---- fragment address constants ----
    const int arl = ((l >> 3) & 1) * 8 + (l & 7);
    uint32_t a0Addr[2][2], a0S[2][2];          // level-0 path
    #pragma unroll
    for (int mt = 0; mt < 2; ++mt)
        #pragma unroll
        for (int tap = 0; tap < 2; ++tap) {
            int row = wm0 + mt * 16 + arl + tap;
            a0Addr[mt][tap] = (uint32_t)row * 256;
            a0S[mt][tap] = (uint32_t)((row & 7) << 4);
        }
    uint32_t aBAddr[4][2], aBS[4][2];          // big path
    #pragma unroll
    for (int mt = 0; mt < 4; ++mt)
        #pragma unroll
        for (int tap = 0; tap < 2; ++tap) {
            int row = wmB + mt * 16 + arl + tap;
            aBAddr[mt][tap] = (uint32_t)row * 256;
            aBS[mt][tap] = (uint32_t)((row & 7) << 4);
        }
    uint32_t bRow[2], bS[2];
    #pragma unroll
    for (int g = 0; g < 2; ++g) {
        int o = wn + g * 16 + ((l >> 4) & 1) * 8 + (l & 7);
        bRow[g] = (uint32_t)o * 512;
        bS[g] = (uint32_t)((o & 7) << 4);
    }
    const uint32_t a_k8b = ((l >> 4) & 1) * 16;
    const uint32_t b_k8b = ((l >> 3) & 1) * 16;
    const uint32_t xswz = ((uint32_t)l * 8) ^ ((uint32_t)wid << 4);
    const int r2 = l >> 2;
    const bool storer = ((r2 & 1) == 0);
    const int o0 = wn /*+nt*8*/ + (l & 3) * 2;   // nt added at use

    int L = N;
    int nlevTot = 0;
    { int t = N; while (t > 1) { t = (t - 1) / 2; nlevTot++; } }

    for (int lvl = 0; L > 1; ++lvl) {
        const int Lout = (L - 1) >> 1;
        const bool final = (Lout == 1);
        uint32_t* YoH = (lvl & 1) ? g_Bh : g_Ah;
        uint32_t* YoL = (lvl & 1) ? g_Bl : g_Al;

        float bx[4], by[4];
        #pragma unroll
        for (int nt = 0; nt < 4; ++nt) {
            float2 bb = *(const float2*)&g_bias[lvl * CCH + wn + nt * 8 + (l & 3) * 2];
            bx[nt] = bb.x; by[nt] = bb.y;
        }

        if (lvl == 0) {
            // =================== level-0 path (R7) ===================
            const int ntiles = (Lout + 31) >> 5;
            int cur = 0;
            if (bid < ntiles) {
                const int pbase = bid << 6;
                #pragma unroll
                for (int s9 = 0; s9 < 9; ++s9) {
                    if (s9 == 8 && wid != 0) break;
                    int row = s9 * 8 + wid;
                    int pin = pbase + row; if (pin > L - 1) pin = L - 1;
                    float4 v = *((const float4*)(Xin + (size_t)perm[pin] * CCH) + l);
                    uint32_t byte = (uint32_t)row * 256 + xswz;
                    cvt_sts(v, sb + X0BUF(0, 0) + byte, sb + X0BUF(0, 1) + byte);
                }
            }
            __syncthreads();

            for (int tile = bid; tile < ntiles; tile += GRIDP) {
                const int nexttile = tile + GRIDP;
                const bool hasnext = nexttile < ntiles;

                float4 pr[9];
                if (hasnext) {
                    const int pbase = nexttile << 6;
                    #pragma unroll
                    for (int s9 = 0; s9 < 9; ++s9) {
                        if (s9 == 8 && wid != 0) break;
                        int row = s9 * 8 + wid;
                        int pin = pbase + row; if (pin > L - 1) pin = L - 1;
                        pr[s9] = *((const float4*)(Xin + (size_t)perm[pin] * CCH) + l);
                    }
                }

                float acc[2][4][4];
                #pragma unroll
                for (int mt = 0; mt < 2; ++mt)
                    #pragma unroll
                    for (int nt = 0; nt < 4; ++nt)
                        #pragma unroll
                        for (int r = 0; r < 4; ++r) acc[mt][nt][r] = 0.f;

                const uint32_t xbH = sb + X0BUF(cur, 0);
                const uint32_t xbL = sb + X0BUF(cur, 1);
                #pragma unroll
                for (int kt = 0; kt < 16; ++kt) {
                    const int tap = kt >> 3;
                    const uint32_t chA = (uint32_t)(kt & 7) * 32 + a_k8b;
                    const uint32_t chB = (uint32_t)kt * 32 + b_k8b;
                    uint32_t Bh[4][2], Bl[4][2];
                    ldx4(Bh[0][0], Bh[0][1], Bh[1][0], Bh[1][1], sb + SM_WH + bRow[0] + (chB ^ bS[0]));
                    ldx4(Bh[2][0], Bh[2][1], Bh[3][0], Bh[3][1], sb + SM_WH + bRow[1] + (chB ^ bS[1]));
                    ldx4(Bl[0][0], Bl[0][1], Bl[1][0], Bl[1][1], sb + SM_WL + bRow[0] + (chB ^ bS[0]));
                    ldx4(Bl[2][0], Bl[2][1], Bl[3][0], Bl[3][1], sb + SM_WL + bRow[1] + (chB ^ bS[1]));
                    #pragma unroll
                    for (int mt = 0; mt < 2; ++mt) {
                        const uint32_t aoff = a0Addr[mt][tap] + (chA ^ a0S[mt][tap]);
                        uint32_t Ah[4], Al[4];
                        ldx4(Ah[0], Ah[1], Ah[2], Ah[3], xbH + aoff);
                        ldx4(Al[0], Al[1], Al[2], Al[3], xbL + aoff);
                        #pragma unroll
                        for (int nt = 0; nt < 4; ++nt) {
                            mma_bf16(acc[mt][nt], Ah, Bh[nt]);
                            mma_bf16(acc[mt][nt], Al, Bh[nt]);
                            mma_bf16(acc[mt][nt], Ah, Bl[nt]);
                        }
                    }
                }

                if (hasnext) {
                    const uint32_t dH = sb + X0BUF(cur ^ 1, 0);
                    const uint32_t dL = sb + X0BUF(cur ^ 1, 1);
                    #pragma unroll
                    for (int s9 = 0; s9 < 9; ++s9) {
                        if (s9 == 8 && wid != 0) break;
                        uint32_t byte = (uint32_t)(s9 * 8 + wid) * 256 + xswz;
                        cvt_sts(pr[s9], dH + byte, dL + byte);
                    }
                }

                // epilogue: bias+leaky+pool -> bf16 packed stage
                #pragma unroll
                for (int mt = 0; mt < 2; ++mt)
                    #pragma unroll
                    for (int nt = 0; nt < 4; ++nt) {
                        float* d = acc[mt][nt];
                        float v0 = d[0] + bx[nt], v1 = d[1] + by[nt];
                        float v2 = d[2] + bx[nt], v3 = d[3] + by[nt];
                        v0 = v0 >= 0.f ? v0 : 0.2f * v0;
                        v1 = v1 >= 0.f ? v1 : 0.2f * v1;
                        v2 = v2 >= 0.f ? v2 : 0.2f * v2;
                        v3 = v3 >= 0.f ? v3 : 0.2f * v3;
                        float u0 = fmaxf(v0, __shfl_xor_sync(0xffffffffu, v0, 4));
                        float u1 = fmaxf(v1, __shfl_xor_sync(0xffffffffu, v1, 4));
                        float u2 = fmaxf(v2, __shfl_xor_sync(0xffffffffu, v2, 4));
                        float u3 = fmaxf(v3, __shfl_xor_sync(0xffffffffu, v3, 4));
                        if (storer) {
                            const int oc = o0 + nt * 8;
                            const int s = (wm0 + mt * 16 + r2) >> 1;   // 0..31
                            uint32_t hp, lp;
                            pack_hl(u0, u1, hp, lp);
                            STS32(sb + SM_STAGE + s * STG_ROW + oc * 2, hp);
                            STS32(sb + SM_STAGE + 8704 + s * STG_ROW + oc * 2, lp);
                            pack_hl(u2, u3, hp, lp);
                            STS32(sb + SM_STAGE + (s + 4) * STG_ROW + oc * 2, hp);
                            STS32(sb + SM_STAGE + 8704 + (s + 4) * STG_ROW + oc * 2, lp);
                        }
                    }
                __syncthreads();

                const int jbase = tile << 5;
                #pragma unroll
                for (int k = 0; k < 4; ++k) {
                    int idx = tid + k * THREADS;             // 0..1023
                    int plane = idx >> 9, rem = idx & 511;
                    int row = rem >> 4, c = rem & 15;
                    if (jbase + row < Lout) {
                        uint4 v = *(const uint4*)(stage + plane * 8704 + row * STG_ROW + c * 16);
                        uint32_t* dst = (plane ? YoL : YoH) + (size_t)(jbase + row) * 64 + c * 4;
                        *(uint4*)dst = v;
                    }
                }
                __syncthreads();
                cur ^= 1;
            }
        } else {
            // =================== levels >= 1 (cp.async, 128-pos tiles) ===================
            const int ntiles = (Lout + 63) >> 6;
            const uint32_t* srcH = (lvl & 1) ? g_Ah : g_Bh;   // previous level's planes
            const uint32_t* srcL = (lvl & 1) ? g_Al : g_Bl;

            if (bid < ntiles) {
                const int pbase = bid << 7;
                for (int i = tid; i < 129 * 16; i += THREADS) {
                    int row = i >> 4, c = i & 15;
                    int ring = pbase + row; if (ring > L - 1) ring = L - 1;
                    uint32_t d = (uint32_t)row * 256 + (((uint32_t)c * 16) ^ (uint32_t)((row & 7) << 4));
                    CP_ASYNC16(sb + XH1 + d, srcH + (size_t)ring * 64 + c * 4);
                    CP_ASYNC16(sb + XL1 + d, srcL + (size_t)ring * 64 + c * 4);
                }
            }
            CP_COMMIT();

            for (int tile = bid; tile < ntiles; tile += GRIDP) {
                CP_WAIT0();
                __syncthreads();

                float acc[4][4][4];
                #pragma unroll
                for (int mt = 0; mt < 4; ++mt)
                    #pragma unroll
                    for (int nt = 0; nt < 4; ++nt)
                        #pragma unroll
                        for (int r = 0; r < 4; ++r) acc[mt][nt][r] = 0.f;

                #pragma unroll
                for (int kt = 0; kt < 16; ++kt) {
                    const int tap = kt >> 3;
                    const uint32_t chA = (uint32_t)(kt & 7) * 32 + a_k8b;
                    const uint32_t chB = (uint32_t)kt * 32 + b_k8b;
                    uint32_t Bh[4][2], Bl[4][2];
                    ldx4(Bh[0][0], Bh[0][1], Bh[1][0], Bh[1][1], sb + SM_WH + bRow[0] + (chB ^ bS[0]));
                    ldx4(Bh[2][0], Bh[2][1], Bh[3][0], Bh[3][1], sb + SM_WH + bRow[1] + (chB ^ bS[1]));
                    ldx4(Bl[0][0], Bl[0][1], Bl[1][0], Bl[1][1], sb + SM_WL + bRow[0] + (chB ^ bS[0]));
                    ldx4(Bl[2][0], Bl[2][1], Bl[3][0], Bl[3][1], sb + SM_WL + bRow[1] + (chB ^ bS[1]));
                    #pragma unroll
                    for (int mt = 0; mt < 4; ++mt) {
                        const uint32_t aoff = aBAddr[mt][tap] + (chA ^ aBS[mt][tap]);
                        uint32_t Ah[4], Al[4];
                        ldx4(Ah[0], Ah[1], Ah[2], Ah[3], sb + XH1 + aoff);
                        ldx4(Al[0], Al[1], Al[2], Al[3], sb + XL1 + aoff);
                        #pragma unroll
                        for (int nt = 0; nt < 4; ++nt) {
                            mma_bf16(acc[mt][nt], Ah, Bh[nt]);
                            mma_bf16(acc[mt][nt], Al, Bh[nt]);
                            mma_bf16(acc[mt][nt], Ah, Bl[nt]);
                        }
                    }
                }
                __syncthreads();   // all X reads done -> buffer reusable

                const int nexttile = tile + GRIDP;
                if (nexttile < ntiles) {
                    const int pbase = nexttile << 7;
                    for (int i = tid; i < 129 * 16; i += THREADS) {
                        int row = i >> 4, c = i & 15;
                        int ring = pbase + row; if (ring > L - 1) ring = L - 1;
                        uint32_t d = (uint32_t)row * 256 + (((uint32_t)c * 16) ^ (uint32_t)((row & 7) << 4));
                        CP_ASYNC16(sb + XH1 + d, srcH + (size_t)ring * 64 + c * 4);
                        CP_ASYNC16(sb + XL1 + d, srcL + (size_t)ring * 64 + c * 4);
                    }
                }
                CP_COMMIT();

                // epilogue: two passes of 32 output rows
                const int jbase = tile << 6;
                #pragma unroll
                for (int h = 0; h < 2; ++h) {
                    #pragma unroll
                    for (int m2 = 0; m2 < 2; ++m2) {
                        const int mt = h * 2 + m2;
                        #pragma unroll
                        for (int nt = 0; nt < 4; ++nt) {
                            float* d = acc[mt][nt];
                            float v0 = d[0] + bx[nt], v1 = d[1] + by[nt];
                            float v2 = d[2] + bx[nt], v3 = d[3] + by[nt];
                            v0 = v0 >= 0.f ? v0 : 0.2f * v0;
                            v1 = v1 >= 0.f ? v1 : 0.2f * v1;
                            v2 = v2 >= 0.f ? v2 : 0.2f * v2;
                            v3 = v3 >= 0.f ? v3 : 0.2f * v3;
                            float u0 = fmaxf(v0, __shfl_xor_sync(0xffffffffu, v0, 4));
                            float u1 = fmaxf(v1, __shfl_xor_sync(0xffffffffu, v1, 4));
                            float u2 = fmaxf(v2, __shfl_xor_sync(0xffffffffu, v2, 4));
                            float u3 = fmaxf(v3, __shfl_xor_sync(0xffffffffu, v3, 4));
                            if (storer) {
                                const int oc = o0 + nt * 8;
                                const int j = (wmB + mt * 16 + r2) >> 1;   // 0..63
                                const int s = (j & 15) | ((j >> 1) & 16);  // 0..31
                                uint32_t hp, lp;
                                pack_hl(u0, u1, hp, lp);
                                STS32(sb + SM_STAGE + s * STG_ROW + oc * 2, hp);
                                STS32(sb + SM_STAGE + 8704 + s * STG_ROW + oc * 2, lp);
                                pack_hl(u2, u3, hp, lp);
                                STS32(sb + SM_STAGE + (s + 4) * STG_ROW + oc * 2, hp);
                                STS32(sb + SM_STAGE + 8704 + (s + 4) * STG_ROW + oc * 2, lp);
                                if (final && j == 0) {
                                    outp[oc] = u0;
                                    outp[oc + 1] = u1;
                                }
                            }
                        }
                    }
                    __syncthreads();
                    #pragma unroll
                    for (int k = 0; k < 4; ++k) {
                        int idx = tid + k * THREADS;
                        int plane = idx >> 9, rem = idx & 511;
                        int row = rem >> 4, c = rem & 15;
                        int j = (row & 15) + (h << 4) + ((row & 16) << 1);
                        if (jbase + j < Lout) {
                            uint4 v = *(const uint4*)(stage + plane * 8704 + row * STG_ROW + c * 16);
                            uint32_t* dst = (plane ? YoL : YoH) + (size_t)(jbase + j) * 64 + c * 4;
                            *(uint4*)dst = v;
                        }
                    }
                    __syncthreads();
                }
            }
        }

        grid_barrier();
        L = Lout;
    }
}

// ---------------------------------------------------------------------------
extern "C" void kernel_launch(void* const* d_in, const int* in_sizes, int n_in,
                              void* d_out, int out_size) {
    const float* x     = (const float*)d_in[0];
    const float* depth = (const float*)d_in[1];
    const float* W     = (const float*)d_in[2];
    const float* b     = (const float*)d_in[3];
    const int*   perm  = (const int*)d_in[4];
    float* out = (float*)d_out;

    int N = in_sizes[0] / CCH;
    int nlev = 0;
    { int L = N; while (L > 1) { L = (L - 1) / 2; nlev++; } }

    cudaFuncSetAttribute((const void*)persistent_kernel,
                         cudaFuncAttributeMaxDynamicSharedMemorySize, SM_TOT);

    precompute_kernel<<<1, 256>>>(W, b, depth, nlev);
    persistent_kernel<<<GRIDP, THREADS, SM_TOT>>>(x, perm, out, N);
}

// round 10
// speedup vs baseline: 2.6222x; 1.0475x over previous
#include <cuda_runtime.h>
#include <cuda_bf16.h>
#include <stdint.h>

#define CCH 128
#define THREADS 256
#define GRIDP 148

// ---- device scratch ----
__device__ float    g_bias[32 * CCH];
__device__ uint32_t g_Wtm[2][CCH][128];     // [hi/lo][o][k/2] bf16x2 of Acat=[W0 W1]
__device__ uint32_t g_Ah[262144 * 64], g_Al[262144 * 64];   // even-level planes
__device__ uint32_t g_Bh[131072 * 64], g_Bl[131072 * 64];   // odd-level planes
__device__ int      g_barCount;
__device__ volatile unsigned g_barGen;

// ---- SMEM layout (bytes) ----
#define XH1 0                       // planes path: 129 rows x 256B
#define XL1 33536
#define X0BUF(b, s) ((s) * 33536 + (b) * 16768)   // level-0 double buffer
#define SM_WH   67072
#define SM_WL   (67072 + 65536)
#define SM_STAGE 198144             // 2 planes x 32 rows x 272B
#define SM_TOT   215552
#define STG_ROW 272

__device__ __forceinline__ uint32_t smem_u32(const void* p) {
    uint32_t a;
    asm("{ .reg .u64 t; cvta.to.shared.u64 t, %1; cvt.u32.u64 %0, t; }" : "=r"(a) : "l"(p));
    return a;
}
__device__ __forceinline__ void ldx4(uint32_t& r0, uint32_t& r1, uint32_t& r2, uint32_t& r3,
                                     uint32_t addr) {
    asm volatile("ldmatrix.sync.aligned.m8n8.x4.shared.b16 {%0,%1,%2,%3}, [%4];"
                 : "=r"(r0), "=r"(r1), "=r"(r2), "=r"(r3) : "r"(addr));
}
__device__ __forceinline__ void mma_bf16(float* d, const uint32_t* a, const uint32_t* b) {
    asm volatile("mma.sync.aligned.m16n8k16.row.col.f32.bf16.bf16.f32 "
                 "{%0,%1,%2,%3}, {%4,%5,%6,%7}, {%8,%9}, {%0,%1,%2,%3};"
                 : "+f"(d[0]), "+f"(d[1]), "+f"(d[2]), "+f"(d[3])
                 : "r"(a[0]), "r"(a[1]), "r"(a[2]), "r"(a[3]), "r"(b[0]), "r"(b[1]));
}
#define STS64(addr, x, y) \
    asm volatile("st.shared.v2.u32 [%0], {%1,%2};" :: "r"(addr), "r"(x), "r"(y) : "memory")
#define STS32(addr, x) \
    asm volatile("st.shared.u32 [%0], %1;" :: "r"(addr), "r"(x) : "memory")
#define CP_ASYNC16(dst, src) \
    asm volatile("cp.async.cg.shared.global [%0], [%1], 16;" :: "r"(dst), "l"(src) : "memory")
#define CP_COMMIT() asm volatile("cp.async.commit_group;" ::: "memory")
#define CP_WAIT0()  asm volatile("cp.async.wait_group 0;" ::: "memory")

__device__ __forceinline__ void cvt_sts(float4 v, uint32_t dstH, uint32_t dstL) {
    __nv_bfloat16 h0 = __float2bfloat16_rn(v.x), h1 = __float2bfloat16_rn(v.y);
    __nv_bfloat16 h2 = __float2bfloat16_rn(v.z), h3 = __float2bfloat16_rn(v.w);
    __nv_bfloat16 l0 = __float2bfloat16_rn(v.x - __bfloat162float(h0));
    __nv_bfloat16 l1 = __float2bfloat16_rn(v.y - __bfloat162float(h1));
    __nv_bfloat16 l2 = __float2bfloat16_rn(v.z - __bfloat162float(h2));
    __nv_bfloat16 l3 = __float2bfloat16_rn(v.w - __bfloat162float(h3));
    __nv_bfloat162 hp0 = {h0, h1}, hp1 = {h2, h3};
    __nv_bfloat162 lp0 = {l0, l1}, lp1 = {l2, l3};
    STS64(dstH, *(uint32_t*)&hp0, *(uint32_t*)&hp1);
    STS64(dstL, *(uint32_t*)&lp0, *(uint32_t*)&lp1);
}
__device__ __forceinline__ void pack_hl(float a, float b, uint32_t& hp, uint32_t& lp) {
    __nv_bfloat16 ha = __float2bfloat16_rn(a), hb = __float2bfloat16_rn(b);
    __nv_bfloat16 la = __float2bfloat16_rn(a - __bfloat162float(ha));
    __nv_bfloat16 lb = __float2bfloat16_rn(b - __bfloat162float(hb));
    __nv_bfloat162 h = {ha, hb}, lo = {la, lb};
    hp = *(uint32_t*)&h; lp = *(uint32_t*)&lo;
}

__device__ __forceinline__ void grid_barrier() {
    __syncthreads();
    if (threadIdx.x == 0) {
        unsigned gen = g_barGen;
        __threadfence();
        if (atomicAdd(&g_barCount, 1) == (int)gridDim.x - 1) {
            g_barCount = 0;
            __threadfence();
            g_barGen = gen + 1;
        } else {
            while (g_barGen == gen) { }
        }
        __threadfence();
    }
    __syncthreads();
}

// ---------------------------------------------------------------------------
__global__ void precompute_kernel(const float* __restrict__ W,
                                  const float* __restrict__ b,
                                  const float* __restrict__ depth,
                                  int nlev) {
    int tid = threadIdx.x;
    for (int i = tid; i < 2 * CCH * 128; i += blockDim.x) {
        int s = i >> 14, o = (i >> 7) & 127, col = i & 127;
        uint32_t out = 0;
        #pragma unroll
        for (int h = 0; h < 2; ++h) {
            int c = 2 * col + h;
            float w = (c < 128) ? W[(size_t)o * 512 + c * 2]
                                : W[(size_t)o * 512 + (c - 128) * 2 + 1];
            __nv_bfloat16 hi = __float2bfloat16_rn(w);
            __nv_bfloat16 v = (s == 0) ? hi
                              : __float2bfloat16_rn(w - __bfloat162float(hi));
            uint16_t bits = *(uint16_t*)&v;
            out |= (uint32_t)bits << (16 * h);
        }
        g_Wtm[s][o][col] = out;
    }
    if (tid < CCH) {
        int o = tid;
        float ws[CCH];
        #pragma unroll 4
        for (int c = 0; c < CCH; ++c)
            ws[c] = W[(size_t)o * 512 + (128 + c) * 2 + 0] +
                    W[(size_t)o * 512 + (128 + c) * 2 + 1];
        for (int lev = 0; lev < nlev; ++lev) {
            float s = b[o];
            #pragma unroll 4
            for (int c = 0; c < CCH; ++c) s += ws[c] * depth[lev * CCH + c];
            g_bias[lev * CCH + o] = s;
        }
    }
}

// ---------------------------------------------------------------------------
// Kernel A: level 0 only (R7 pipeline), outputs bf16 hi/lo planes to g_Ah/g_Al.
// ---------------------------------------------------------------------------
__global__ __launch_bounds__(THREADS)
void level0_kernel(const float* __restrict__ Xin, const int* __restrict__ perm, int N) {
    extern __shared__ char smem[];
    const uint32_t sb = smem_u32(smem);
    char* stage = smem + SM_STAGE;
    const int tid = threadIdx.x, l = tid & 31, wid = tid >> 5;
    const int wm = (wid >> 2) * 32, wn = (wid & 3) * 32;
    const int bid = blockIdx.x;
    const int L = N, Lout = (N - 1) >> 1;
    const int ntiles = (Lout + 31) >> 5;

    for (int i = tid; i < 2 * 128 * 64; i += THREADS) {
        int split = i >> 13, rem = i & 8191, o = rem >> 6, u = rem & 63;
        uint2 v = ((const uint2*)&g_Wtm[split][o][0])[u];
        uint32_t byte = (uint32_t)o * 512 + (((uint32_t)u * 8) ^ (uint32_t)((o & 7) << 4));
        STS64(sb + (split ? SM_WL : SM_WH) + byte, v.x, v.y);
    }

    const int arl = ((l >> 3) & 1) * 8 + (l & 7);
    uint32_t aAddr[2][2], aS[2][2];
    #pragma unroll
    for (int mt = 0; mt < 2; ++mt)
        #pragma unroll
        for (int tap = 0; tap < 2; ++tap) {
            int row = wm + mt * 16 + arl + tap;
            aAddr[mt][tap] = (uint32_t)row * 256;
            aS[mt][tap] = (uint32_t)((row & 7) << 4);
        }
    uint32_t bRow[2], bS[2];
    #pragma unroll
    for (int g = 0; g < 2; ++g) {
        int o = wn + g * 16 + ((l >> 4) & 1) * 8 + (l & 7);
        bRow[g] = (uint32_t)o * 512;
        bS[g] = (uint32_t)((o & 7) << 4);
    }
    const uint32_t a_k8b = ((l >> 4) & 1) * 16;
    const uint32_t b_k8b = ((l >> 3) & 1) * 16;
    const uint32_t xswz = ((uint32_t)l * 8) ^ ((uint32_t)wid << 4);
    const int r2 = l >> 2;
    const bool storer = ((r2 & 1) == 0);
    const int o0 = wn + (l & 3) * 2;

    float bx[4], by[4];
    #pragma unroll
    for (int nt = 0; nt < 4; ++nt) {
        float2 bb = *(const float2*)&g_bias[wn + nt * 8 + (l & 3) * 2];
        bx[nt] = bb.x; by[nt] = bb.y;
    }

    int cur = 0;
    if (bid < ntiles) {
        const int pbase = bid << 6;
        #pragma unroll
        for (int s9 = 0; s9 < 9; ++s9) {
            if (s9 == 8 && wid != 0) break;
            int row = s9 * 8 + wid;
            int pin = pbase + row; if (pin > L - 1) pin = L - 1;
            float4 v = *((const float4*)(Xin + (size_t)perm[pin] * CCH) + l);
            uint32_t byte = (uint32_t)row * 256 + xswz;
            cvt_sts(v, sb + X0BUF(0, 0) + byte, sb + X0BUF(0, 1) + byte);
        }
    }
    __syncthreads();

    for (int tile = bid; tile < ntiles; tile += GRIDP) {
        const int nexttile = tile + GRIDP;
        const bool hasnext = nexttile < ntiles;

        float4 pr[9];
        if (hasnext) {
            const int pbase = nexttile << 6;
            #pragma unroll
            for (int s9 = 0; s9 < 9; ++s9) {
                if (s9 == 8 && wid != 0) break;
                int row = s9 * 8 + wid;
                int pin = pbase + row; if (pin > L - 1) pin = L - 1;
                pr[s9] = *((const float4*)(Xin + (size_t)perm[pin] * CCH) + l);
            }
        }

        float acc[2][4][4];
        #pragma unroll
        for (int mt = 0; mt < 2; ++mt)
            #pragma unroll
            for (int nt = 0; nt < 4; ++nt)
                #pragma unroll
                for (int r = 0; r < 4; ++r) acc[mt][nt][r] = 0.f;

        const uint32_t xbH = sb + X0BUF(cur, 0);
        const uint32_t xbL = sb + X0BUF(cur, 1);
        #pragma unroll
        for (int kt = 0; kt < 16; ++kt) {
            const int tap = kt >> 3;
            const uint32_t chA = (uint32_t)(kt & 7) * 32 + a_k8b;
            const uint32_t chB = (uint32_t)kt * 32 + b_k8b;
            uint32_t Bh[4][2], Bl[4][2];
            ldx4(Bh[0][0], Bh[0][1], Bh[1][0], Bh[1][1], sb + SM_WH + bRow[0] + (chB ^ bS[0]));
            ldx4(Bh[2][0], Bh[2][1], Bh[3][0], Bh[3][1], sb + SM_WH + bRow[1] + (chB ^ bS[1]));
            ldx4(Bl[0][0], Bl[0][1], Bl[1][0], Bl[1][1], sb + SM_WL + bRow[0] + (chB ^ bS[0]));
            ldx4(Bl[2][0], Bl[2][1], Bl[3][0], Bl[3][1], sb + SM_WL + bRow[1] + (chB ^ bS[1]));
            #pragma unroll
            for (int mt = 0; mt < 2; ++mt) {
                const uint32_t aoff = aAddr[mt][tap] + (chA ^ aS[mt][tap]);
                uint32_t Ah[4], Al[4];
                ldx4(Ah[0], Ah[1], Ah[2], Ah[3], xbH + aoff);
                ldx4(Al[0], Al[1], Al[2], Al[3], xbL + aoff);
                #pragma unroll
                for (int nt = 0; nt < 4; ++nt) {
                    mma_bf16(acc[mt][nt], Ah, Bh[nt]);
                    mma_bf16(acc[mt][nt], Al, Bh[nt]);
                    mma_bf16(acc[mt][nt], Ah, Bl[nt]);
                }
            }
        }

        if (hasnext) {
            const uint32_t dH = sb + X0BUF(cur ^ 1, 0);
            const uint32_t dL = sb + X0BUF(cur ^ 1, 1);
            #pragma unroll
            for (int s9 = 0; s9 < 9; ++s9) {
                if (s9 == 8 && wid != 0) break;
                uint32_t byte = (uint32_t)(s9 * 8 + wid) * 256 + xswz;
                cvt_sts(pr[s9], dH + byte, dL + byte);
            }
        }

        #pragma unroll
        for (int mt = 0; mt < 2; ++mt)
            #pragma unroll
            for (int nt = 0; nt < 4; ++nt) {
                float* d = acc[mt][nt];
                float v0 = d[0] + bx[nt], v1 = d[1] + by[nt];
                float v2 = d[2] + bx[nt], v3 = d[3] + by[nt];
                v0 = v0 >= 0.f ? v0 : 0.2f * v0;
                v1 = v1 >= 0.f ? v1 : 0.2f * v1;
                v2 = v2 >= 0.f ? v2 : 0.2f * v2;
                v3 = v3 >= 0.f ? v3 : 0.2f * v3;
                float u0 = fmaxf(v0, __shfl_xor_sync(0xffffffffu, v0, 4));
                float u1 = fmaxf(v1, __shfl_xor_sync(0xffffffffu, v1, 4));
                float u2 = fmaxf(v2, __shfl_xor_sync(0xffffffffu, v2, 4));
                float u3 = fmaxf(v3, __shfl_xor_sync(0xffffffffu, v3, 4));
                if (storer) {
                    const int oc = o0 + nt * 8;
                    const int s = (wm + mt * 16 + r2) >> 1;   // 0..31
                    uint32_t hp, lp;
                    pack_hl(u0, u1, hp, lp);
                    STS32(sb + SM_STAGE + s * STG_ROW + oc * 2, hp);
                    STS32(sb + SM_STAGE + 8704 + s * STG_ROW + oc * 2, lp);
                    pack_hl(u2, u3, hp, lp);
                    STS32(sb + SM_STAGE + (s + 4) * STG_ROW + oc * 2, hp);
                    STS32(sb + SM_STAGE + 8704 + (s + 4) * STG_ROW + oc * 2, lp);
                }
            }
        __syncthreads();

        const int jbase = tile << 5;
        #pragma unroll
        for (int k = 0; k < 4; ++k) {
            int idx = tid + k * THREADS;
            int plane = idx >> 9, rem = idx & 511;
            int row = rem >> 4, c = rem & 15;
            if (jbase + row < Lout) {
                uint4 v = *(const uint4*)(stage + plane * 8704 + row * STG_ROW + c * 16);
                uint32_t* dst = (plane ? g_Al : g_Ah) + (size_t)(jbase + row) * 64 + c * 4;
                *(uint4*)dst = v;
            }
        }
        __syncthreads();
        cur ^= 1;
    }
}

// ---------------------------------------------------------------------------
// Kernel B: persistent, levels 1..end. cp.async bf16 planes; per level
// 128-pos tiles (Lout > 4736) or 64-pos tiles; final level writes fp32 out.
// ---------------------------------------------------------------------------
__global__ __launch_bounds__(THREADS)
void levels_kernel(float* __restrict__ outp, int L0out) {
    extern __shared__ char smem[];
    const uint32_t sb = smem_u32(smem);
    char* stage = smem + SM_STAGE;
    const int tid = threadIdx.x, l = tid & 31, wid = tid >> 5;
    const int wn = (wid & 3) * 32;
    const int wm0 = (wid >> 2) * 32;
    const int wmB = (wid >> 2) * 64;
    const int bid = blockIdx.x;

    for (int i = tid; i < 2 * 128 * 64; i += THREADS) {
        int split = i >> 13, rem = i & 8191, o = rem >> 6, u = rem & 63;
        uint2 v = ((const uint2*)&g_Wtm[split][o][0])[u];
        uint32_t byte = (uint32_t)o * 512 + (((uint32_t)u * 8) ^ (uint32_t)((o & 7) << 4));
        STS64(sb + (split ? SM_WL : SM_WH) + byte, v.x, v.y);
    }

    const int arl = ((l >> 3) & 1) * 8 + (l & 7);
    uint32_t aBAddr[4][2], aBS[4][2];
    #pragma unroll
    for (int mt = 0; mt < 4; ++mt)
        #pragma unroll
        for (int tap = 0; tap < 2; ++tap) {
            int row = wmB + mt * 16 + arl + tap;
            aBAddr[mt][tap] = (uint32_t)row * 256;
            aBS[mt][tap] = (uint32_t)((row & 7) << 4);
        }
    uint32_t a0Addr[2][2], a0S[2][2];
    #pragma unroll
    for (int mt = 0; mt < 2; ++mt)
        #pragma unroll
        for (int tap = 0; tap < 2; ++tap) {
            int row = wm0 + mt * 16 + arl + tap;
            a0Addr[mt][tap] = (uint32_t)row * 256;
            a0S[mt][tap] = (uint32_t)((row & 7) << 4);
        }
    uint32_t bRow[2], bS[2];
    #pragma unroll
    for (int g = 0; g < 2; ++g) {
        int o = wn + g * 16 + ((l >> 4) & 1) * 8 + (l & 7);
        bRow[g] = (uint32_t)o * 512;
        bS[g] = (uint32_t)((o & 7) << 4);
    }
    const uint32_t a_k8b = ((l >> 4) & 1) * 16;
    const uint32_t b_k8b = ((l >> 3) & 1) * 16;
    const int r2 = l >> 2;
    const bool storer = ((r2 & 1) == 0);
    const int o0 = wn + (l & 3) * 2;

    int L = L0out;
    for (int lvl = 1; L > 1; ++lvl) {
        const int Lout = (L - 1) >> 1;
        const bool final = (Lout == 1);
        const bool big = (Lout > 4736);
        const int tileP = big ? 128 : 64;
        const int tileJ = big ? 64 : 32;
        const int nrows = tileP + 1;
        const int ntiles = (Lout + tileJ - 1) / tileJ;
        uint32_t* YoH = (lvl & 1) ? g_Bh : g_Ah;
        uint32_t* YoL = (lvl & 1) ? g_Bl : g_Al;
        const uint32_t* srcH = (lvl & 1) ? g_Ah : g_Bh;
        const uint32_t* srcL = (lvl & 1) ? g_Al : g_Bl;

        float bx[4], by[4];
        #pragma unroll
        for (int nt = 0; nt < 4; ++nt) {
            float2 bb = *(const float2*)&g_bias[lvl * CCH + wn + nt * 8 + (l & 3) * 2];
            bx[nt] = bb.x; by[nt] = bb.y;
        }

        if (bid < ntiles) {
            const int pbase = bid * tileP;
            for (int i = tid; i < nrows * 16; i += THREADS) {
                int row = i >> 4, c = i & 15;
                int ring = pbase + row; if (ring > L - 1) ring = L - 1;
                uint32_t d = (uint32_t)row * 256 + (((uint32_t)c * 16) ^ (uint32_t)((row & 7) << 4));
                CP_ASYNC16(sb + XH1 + d, srcH + (size_t)ring * 64 + c * 4);
                CP_ASYNC16(sb + XL1 + d, srcL + (size_t)ring * 64 + c * 4);
            }
        }
        CP_COMMIT();

        for (int tile = bid; tile < ntiles; tile += GRIDP) {
            CP_WAIT0();
            __syncthreads();

            float acc[4][4][4];
            const int mtN = big ? 4 : 2;
            #pragma unroll
            for (int mt = 0; mt < 4; ++mt)
                #pragma unroll
                for (int nt = 0; nt < 4; ++nt)
                    #pragma unroll
                    for (int r = 0; r < 4; ++r) acc[mt][nt][r] = 0.f;

            if (big) {
                #pragma unroll
                for (int kt = 0; kt < 16; ++kt) {
                    const int tap = kt >> 3;
                    const uint32_t chA = (uint32_t)(kt & 7) * 32 + a_k8b;
                    const uint32_t chB = (uint32_t)kt * 32 + b_k8b;
                    uint32_t Bh[4][2], Bl[4][2];
                    ldx4(Bh[0][0], Bh[0][1], Bh[1][0], Bh[1][1], sb + SM_WH + bRow[0] + (chB ^ bS[0]));
                    ldx4(Bh[2][0], Bh[2][1], Bh[3][0], Bh[3][1], sb + SM_WH + bRow[1] + (chB ^ bS[1]));
                    ldx4(Bl[0][0], Bl[0][1], Bl[1][0], Bl[1][1], sb + SM_WL + bRow[0] + (chB ^ bS[0]));
                    ldx4(Bl[2][0], Bl[2][1], Bl[3][0], Bl[3][1], sb + SM_WL + bRow[1] + (chB ^ bS[1]));
                    #pragma unroll
                    for (int mt = 0; mt < 4; ++mt) {
                        const uint32_t aoff = aBAddr[mt][tap] + (chA ^ aBS[mt][tap]);
                        uint32_t Ah[4], Al[4];
                        ldx4(Ah[0], Ah[1], Ah[2], Ah[3], sb + XH1 + aoff);
                        ldx4(Al[0], Al[1], Al[2], Al[3], sb + XL1 + aoff);
                        #pragma unroll
                        for (int nt = 0; nt < 4; ++nt) {
                            mma_bf16(acc[mt][nt], Ah, Bh[nt]);
                            mma_bf16(acc[mt][nt], Al, Bh[nt]);
                            mma_bf16(acc[mt][nt], Ah, Bl[nt]);
                        }
                    }
                }
            } else {
                #pragma unroll
                for (int kt = 0; kt < 16; ++kt) {
                    const int tap = kt >> 3;
                    const uint32_t chA = (uint32_t)(kt & 7) * 32 + a_k8b;
                    const uint32_t chB = (uint32_t)kt * 32 + b_k8b;
                    uint32_t Bh[4][2], Bl[4][2];
                    ldx4(Bh[0][0], Bh[0][1], Bh[1][0], Bh[1][1], sb + SM_WH + bRow[0] + (chB ^ bS[0]));
                    ldx4(Bh[2][0], Bh[2][1], Bh[3][0], Bh[3][1], sb + SM_WH + bRow[1] + (chB ^ bS[1]));
                    ldx4(Bl[0][0], Bl[0][1], Bl[1][0], Bl[1][1], sb + SM_WL + bRow[0] + (chB ^ bS[0]));
                    ldx4(Bl[2][0], Bl[2][1], Bl[3][0], Bl[3][1], sb + SM_WL + bRow[1] + (chB ^ bS[1]));
                    #pragma unroll
                    for (int mt = 0; mt < 2; ++mt) {
                        const uint32_t aoff = a0Addr[mt][tap] + (chA ^ a0S[mt][tap]);
                        uint32_t Ah[4], Al[4];
                        ldx4(Ah[0], Ah[1], Ah[2], Ah[3], sb + XH1 + aoff);
                        ldx4(Al[0], Al[1], Al[2], Al[3], sb + XL1 + aoff);
                        #pragma unroll
                        for (int nt = 0; nt < 4; ++nt) {
                            mma_bf16(acc[mt][nt], Ah, Bh[nt]);
                            mma_bf16(acc[mt][nt], Al, Bh[nt]);
                            mma_bf16(acc[mt][nt], Ah, Bl[nt]);
                        }
                    }
                }
            }
            __syncthreads();   // X reads done -> buffer reusable

            const int nexttile = tile + GRIDP;
            if (nexttile < ntiles) {
                const int pbase = nexttile * tileP;
                for (int i = tid; i < nrows * 16; i += THREADS) {
                    int row = i >> 4, c = i & 15;
                    int ring = pbase + row; if (ring > L - 1) ring = L - 1;
                    uint32_t d = (uint32_t)row * 256 + (((uint32_t)c * 16) ^ (uint32_t)((row & 7) << 4));
                    CP_ASYNC16(sb + XH1 + d, srcH + (size_t)ring * 64 + c * 4);
                    CP_ASYNC16(sb + XL1 + d, srcL + (size_t)ring * 64 + c * 4);
                }
            }
            CP_COMMIT();

            const int jbase = tile * tileJ;
            const int hN = big ? 2 : 1;
            for (int h = 0; h < hN; ++h) {
                #pragma unroll
                for (int m2 = 0; m2 < 2; ++m2) {
                    const int mt = h * 2 + m2;
                    const int wmX = big ? wmB : wm0;
                    #pragma unroll
                    for (int nt = 0; nt < 4; ++nt) {
                        float* d = acc[mt][nt];
                        float v0 = d[0] + bx[nt], v1 = d[1] + by[nt];
                        float v2 = d[2] + bx[nt], v3 = d[3] + by[nt];
                        v0 = v0 >= 0.f ? v0 : 0.2f * v0;
                        v1 = v1 >= 0.f ? v1 : 0.2f * v1;
                        v2 = v2 >= 0.f ? v2 : 0.2f * v2;
                        v3 = v3 >= 0.f ? v3 : 0.2f * v3;
                        float u0 = fmaxf(v0, __shfl_xor_sync(0xffffffffu, v0, 4));
                        float u1 = fmaxf(v1, __shfl_xor_sync(0xffffffffu, v1, 4));
                        float u2 = fmaxf(v2, __shfl_xor_sync(0xffffffffu, v2, 4));
                        float u3 = fmaxf(v3, __shfl_xor_sync(0xffffffffu, v3, 4));
                        if (storer) {
                            const int oc = o0 + nt * 8;
                            const int j = (wmX + mt * 16 + r2) >> 1;
                            const int s = big ? ((j & 15) | ((j >> 1) & 16)) : j;
                            uint32_t hp, lp;
                            pack_hl(u0, u1, hp, lp);
                            STS32(sb + SM_STAGE + s * STG_ROW + oc * 2, hp);
                            STS32(sb + SM_STAGE + 8704 + s * STG_ROW + oc * 2, lp);
                            pack_hl(u2, u3, hp, lp);
                            STS32(sb + SM_STAGE + (s + 4) * STG_ROW + oc * 2, hp);
                            STS32(sb + SM_STAGE + 8704 + (s + 4) * STG_ROW + oc * 2, lp);
                            if (final && j == 0) {
                                outp[oc] = u0;
                                outp[oc + 1] = u1;
                            }
                        }
                    }
                }
                __syncthreads();
                #pragma unroll
                for (int k = 0; k < 4; ++k) {
                    int idx = tid + k * THREADS;
                    int plane = idx >> 9, rem = idx & 511;
                    int row = rem >> 4, c = rem & 15;
                    int j = big ? ((row & 15) + (h << 4) + ((row & 16) << 1)) : row;
                    if (jbase + j < Lout) {
                        uint4 v = *(const uint4*)(stage + plane * 8704 + row * STG_ROW + c * 16);
                        uint32_t* dst = (plane ? YoL : YoH) + (size_t)(jbase + j) * 64 + c * 4;
                        *(uint4*)dst = v;
                    }
                }
                __syncthreads();
            }
        }

        grid_barrier();
        L = Lout;
    }
}

// ---------------------------------------------------------------------------
extern "C" void kernel_launch(void* const* d_in, const int* in_sizes, int n_in,
                              void* d_out, int out_size) {
    const float* x     = (const float*)d_in[0];
    const float* depth = (const float*)d_in[1];
    const float* W     = (const float*)d_in[2];
    const float* b     = (const float*)d_in[3];
    const int*   perm  = (const int*)d_in[4];
    float* out = (float*)d_out;

    int N = in_sizes[0] / CCH;
    int nlev = 0;
    { int L = N; while (L > 1) { L = (L - 1) / 2; nlev++; } }

    cudaFuncSetAttribute((const void*)level0_kernel,
                         cudaFuncAttributeMaxDynamicSharedMemorySize, SM_TOT);
    cudaFuncSetAttribute((const void*)levels_kernel,
                         cudaFuncAttributeMaxDynamicSharedMemorySize, SM_TOT);

    precompute_kernel<<<1, 256>>>(W, b, depth, nlev);
    level0_kernel<<<GRIDP, THREADS, SM_TOT>>>(x, perm, N);
    levels_kernel<<<GRIDP, THREADS, SM_TOT>>>(out, (N - 1) / 2);
}

// round 11
// speedup vs baseline: 3.2413x; 1.2361x over previous
#include <cuda_runtime.h>
#include <cuda_bf16.h>
#include <stdint.h>

#define CCH 128
#define THREADS 256
#define GRIDP 148            // persistent grid: 1 CTA/SM, all co-resident

// ---- device scratch ----
__device__ float    g_bias[32 * CCH];
__device__ uint32_t g_Wtm[2][CCH][128];     // [hi/lo][o][k/2] bf16x2 of Acat=[W0 W1]
__device__ float    g_bufA[262144 * 128];
__device__ float    g_bufB[131072 * 128];
__device__ int      g_barCount;
__device__ volatile unsigned g_barGen;

// ---- SMEM layout (bytes) ----
// X double buffer: [buf][split] 65 rows x 256B = 16640 each
#define XBUF(buf, split) ((buf) * 33280 + (split) * 16640)
#define SM_WH  66560                 // W hi: 128 rows x 512B
#define SM_WL  (66560 + 65536)
#define SM_STAGE 197632              // 32 rows x 136 floats = 17408 B
#define SM_TOT  215040
#define STAGE_STRIDE 136

__device__ __forceinline__ uint32_t smem_u32(const void* p) {
    uint32_t a;
    asm("{ .reg .u64 t; cvta.to.shared.u64 t, %1; cvt.u32.u64 %0, t; }" : "=r"(a) : "l"(p));
    return a;
}
__device__ __forceinline__ void ldx4(uint32_t& r0, uint32_t& r1, uint32_t& r2, uint32_t& r3,
                                     uint32_t addr) {
    asm volatile("ldmatrix.sync.aligned.m8n8.x4.shared.b16 {%0,%1,%2,%3}, [%4];"
                 : "=r"(r0), "=r"(r1), "=r"(r2), "=r"(r3) : "r"(addr));
}
__device__ __forceinline__ void mma_bf16(float* d, const uint32_t* a, const uint32_t* b) {
    asm volatile("mma.sync.aligned.m16n8k16.row.col.f32.bf16.bf16.f32 "
                 "{%0,%1,%2,%3}, {%4,%5,%6,%7}, {%8,%9}, {%0,%1,%2,%3};"
                 : "+f"(d[0]), "+f"(d[1]), "+f"(d[2]), "+f"(d[3])
                 : "r"(a[0]), "r"(a[1]), "r"(a[2]), "r"(a[3]), "r"(b[0]), "r"(b[1]));
}
#define STS64(addr, x, y) \
    asm volatile("st.shared.v2.u32 [%0], {%1,%2};" :: "r"(addr), "r"(x), "r"(y) : "memory")

__device__ __forceinline__ void cvt_sts(float4 v, uint32_t dstH, uint32_t dstL) {
    __nv_bfloat16 h0 = __float2bfloat16_rn(v.x), h1 = __float2bfloat16_rn(v.y);
    __nv_bfloat16 h2 = __float2bfloat16_rn(v.z), h3 = __float2bfloat16_rn(v.w);
    __nv_bfloat16 l0 = __float2bfloat16_rn(v.x - __bfloat162float(h0));
    __nv_bfloat16 l1 = __float2bfloat16_rn(v.y - __bfloat162float(h1));
    __nv_bfloat16 l2 = __float2bfloat16_rn(v.z - __bfloat162float(h2));
    __nv_bfloat16 l3 = __float2bfloat16_rn(v.w - __bfloat162float(h3));
    __nv_bfloat162 hp0 = {h0, h1}, hp1 = {h2, h3};
    __nv_bfloat162 lp0 = {l0, l1}, lp1 = {l2, l3};
    STS64(dstH, *(uint32_t*)&hp0, *(uint32_t*)&hp1);
    STS64(dstL, *(uint32_t*)&lp0, *(uint32_t*)&lp1);
}

// sense-reversing grid barrier; safe: all GRIDP CTAs co-resident (1 CTA/SM).
__device__ __forceinline__ void grid_barrier() {
    __syncthreads();
    if (threadIdx.x == 0) {
        unsigned gen = g_barGen;
        __threadfence();
        if (atomicAdd(&g_barCount, 1) == (int)gridDim.x - 1) {
            g_barCount = 0;
            __threadfence();
            g_barGen = gen + 1;
        } else {
            while (g_barGen == gen) { }
        }
        __threadfence();
    }
    __syncthreads();
}

// ---------------------------------------------------------------------------
// Parallel precompute: g_Wtm grid-strided; per-level bias one warp per
// (level, o) pair with lane-parallel dot + shfl reduction.
// ---------------------------------------------------------------------------
__global__ void precompute_kernel(const float* __restrict__ W,
                                  const float* __restrict__ b,
                                  const float* __restrict__ depth,
                                  int nlev) {
    const int tid = threadIdx.x;
    const int gid = blockIdx.x * blockDim.x + tid;
    const int gsize = gridDim.x * blockDim.x;

    for (int i = gid; i < 2 * CCH * 128; i += gsize) {
        int s = i >> 14, o = (i >> 7) & 127, col = i & 127;
        uint32_t out = 0;
        #pragma unroll
        for (int h = 0; h < 2; ++h) {
            int c = 2 * col + h;
            float w = (c < 128) ? W[(size_t)o * 512 + c * 2]
                                : W[(size_t)o * 512 + (c - 128) * 2 + 1];
            __nv_bfloat16 hi = __float2bfloat16_rn(w);
            __nv_bfloat16 v = (s == 0) ? hi
                              : __float2bfloat16_rn(w - __bfloat162float(hi));
            uint16_t bits = *(uint16_t*)&v;
            out |= (uint32_t)bits << (16 * h);
        }
        g_Wtm[s][o][col] = out;
    }

    const int l = tid & 31;
    const int gw = gid >> 5;
    const int nwarps = gsize >> 5;
    for (int p = gw; p < nlev * CCH; p += nwarps) {
        const int lev = p >> 7, o = p & 127;
        float s = 0.f;
        #pragma unroll
        for (int cc = 0; cc < 4; ++cc) {
            int c = l + cc * 32;
            float ws = W[(size_t)o * 512 + (128 + c) * 2 + 0] +
                       W[(size_t)o * 512 + (128 + c) * 2 + 1];
            s += ws * depth[lev * CCH + c];
        }
        #pragma unroll
        for (int d = 16; d > 0; d >>= 1)
            s += __shfl_xor_sync(0xffffffffu, s, d);
        if (l == 0) g_bias[lev * CCH + o] = b[o] + s;
    }
}

// ---------------------------------------------------------------------------
// Persistent: all levels, one launch; grid barrier between levels.
// Per level: pipelined 64-position tiles (double-buffered X). (R7 proven.)
// ---------------------------------------------------------------------------
__global__ __launch_bounds__(THREADS)
void persistent_kernel(const float* __restrict__ Xin, const int* __restrict__ perm,
                       float* bufA, float* bufB, float* outp, int N) {
    extern __shared__ char smem[];
    const uint32_t sb = smem_u32(smem);
    float* stagef = (float*)(smem + SM_STAGE);
    const int tid = threadIdx.x, l = tid & 31, wid = tid >> 5;
    const int wm = (wid >> 2) * 32, wn = (wid & 3) * 32;
    const int bid = blockIdx.x;

    // ---- W -> smem once for the whole run ----
    for (int i = tid; i < 2 * 128 * 64; i += THREADS) {
        int split = i >> 13, rem = i & 8191, o = rem >> 6, u = rem & 63;
        uint2 v = ((const uint2*)&g_Wtm[split][o][0])[u];
        uint32_t byte = (uint32_t)o * 512 + (((uint32_t)u * 8) ^ (uint32_t)((o & 7) << 4));
        STS64(sb + (split ? SM_WL : SM_WH) + byte, v.x, v.y);
    }

    // ---- per-lane fragment address constants ----
    const int arl = ((l >> 3) & 1) * 8 + (l & 7);
    uint32_t aAddr[2][2], aS[2][2];
    #pragma unroll
    for (int mt = 0; mt < 2; ++mt)
        #pragma unroll
        for (int tap = 0; tap < 2; ++tap) {
            int row = wm + mt * 16 + arl + tap;
            aAddr[mt][tap] = (uint32_t)row * 256;
            aS[mt][tap] = (uint32_t)((row & 7) << 4);
        }
    uint32_t bRow[2], bS[2];
    #pragma unroll
    for (int g = 0; g < 2; ++g) {
        int o = wn + g * 16 + ((l >> 4) & 1) * 8 + (l & 7);
        bRow[g] = (uint32_t)o * 512;
        bS[g] = (uint32_t)((o & 7) << 4);
    }
    const uint32_t a_k8b = ((l >> 4) & 1) * 16;
    const uint32_t b_k8b = ((l >> 3) & 1) * 16;
    const uint32_t xswz = ((uint32_t)l * 8) ^ ((uint32_t)wid << 4);

    const float* Xcur = Xin;
    int L = N;

    for (int lvl = 0; L > 1; ++lvl) {
        const int Lout = (L - 1) >> 1;
        float* Yout = (Lout == 1) ? outp : ((lvl & 1) ? bufB : bufA);
        const int* pm = (lvl == 0) ? perm : nullptr;
        const int ntiles = (Lout + 31) >> 5;

        float bx[4], by[4];
        #pragma unroll
        for (int nt = 0; nt < 4; ++nt) {
            float2 bb = *(const float2*)&g_bias[lvl * CCH + wn + nt * 8 + (l & 3) * 2];
            bx[nt] = bb.x; by[nt] = bb.y;
        }

        // ---- prologue: load first tile into buf 0 ----
        int cur = 0;
        if (bid < ntiles) {
            const int pbase = bid << 6;
            #pragma unroll
            for (int s9 = 0; s9 < 9; ++s9) {
                if (s9 == 8 && wid != 0) break;
                int row = s9 * 8 + wid;
                int pin = pbase + row; if (pin > L - 1) pin = L - 1;
                size_t srow = pm ? (size_t)pm[pin] : (size_t)pin;
                float4 v = *((const float4*)(Xcur + srow * CCH) + l);
                uint32_t byte = (uint32_t)row * 256 + xswz;
                cvt_sts(v, sb + XBUF(0, 0) + byte, sb + XBUF(0, 1) + byte);
            }
        }
        __syncthreads();

        for (int tile = bid; tile < ntiles; tile += GRIDP) {
            const int nexttile = tile + GRIDP;
            const bool hasnext = nexttile < ntiles;

            // ---- 1. prefetch next tile's X into registers ----
            float4 pr[9];
            if (hasnext) {
                const int pbase = nexttile << 6;
                #pragma unroll
                for (int s9 = 0; s9 < 9; ++s9) {
                    if (s9 == 8 && wid != 0) break;
                    int row = s9 * 8 + wid;
                    int pin = pbase + row; if (pin > L - 1) pin = L - 1;
                    size_t srow = pm ? (size_t)pm[pin] : (size_t)pin;
                    pr[s9] = *((const float4*)(Xcur + srow * CCH) + l);
                }
            }

            // ---- 2. MMA from buf[cur] ----
            float acc[2][4][4];
            #pragma unroll
            for (int mt = 0; mt < 2; ++mt)
                #pragma unroll
                for (int nt = 0; nt < 4; ++nt)
                    #pragma unroll
                    for (int r = 0; r < 4; ++r) acc[mt][nt][r] = 0.f;

            const uint32_t xbH = sb + XBUF(cur, 0);
            const uint32_t xbL = sb + XBUF(cur, 1);
            #pragma unroll
            for (int kt = 0; kt < 16; ++kt) {
                const int tap = kt >> 3;
                const uint32_t chA = (uint32_t)(kt & 7) * 32 + a_k8b;
                const uint32_t chB = (uint32_t)kt * 32 + b_k8b;

                uint32_t Bh[4][2], Bl[4][2];
                ldx4(Bh[0][0], Bh[0][1], Bh[1][0], Bh[1][1], sb + SM_WH + bRow[0] + (chB ^ bS[0]));
                ldx4(Bh[2][0], Bh[2][1], Bh[3][0], Bh[3][1], sb + SM_WH + bRow[1] + (chB ^ bS[1]));
                ldx4(Bl[0][0], Bl[0][1], Bl[1][0], Bl[1][1], sb + SM_WL + bRow[0] + (chB ^ bS[0]));
                ldx4(Bl[2][0], Bl[2][1], Bl[3][0], Bl[3][1], sb + SM_WL + bRow[1] + (chB ^ bS[1]));

                #pragma unroll
                for (int mt = 0; mt < 2; ++mt) {
                    const uint32_t aoff = aAddr[mt][tap] + (chA ^ aS[mt][tap]);
                    uint32_t Ah[4], Al[4];
                    ldx4(Ah[0], Ah[1], Ah[2], Ah[3], xbH + aoff);
                    ldx4(Al[0], Al[1], Al[2], Al[3], xbL + aoff);
                    #pragma unroll
                    for (int nt = 0; nt < 4; ++nt) {
                        mma_bf16(acc[mt][nt], Ah, Bh[nt]);
                        mma_bf16(acc[mt][nt], Al, Bh[nt]);
                        mma_bf16(acc[mt][nt], Ah, Bl[nt]);
                    }
                }
            }

            // ---- 3. cvt + STS prefetched tile into buf[cur^1] ----
            if (hasnext) {
                const uint32_t dH = sb + XBUF(cur ^ 1, 0);
                const uint32_t dL = sb + XBUF(cur ^ 1, 1);
                #pragma unroll
                for (int s9 = 0; s9 < 9; ++s9) {
                    if (s9 == 8 && wid != 0) break;
                    uint32_t byte = (uint32_t)(s9 * 8 + wid) * 256 + xswz;
                    cvt_sts(pr[s9], dH + byte, dL + byte);
                }
            }

            // ---- 4. epilogue: bias + leaky + pool(2) -> stage ----
            const int r2 = l >> 2;
            const bool storer = ((r2 & 1) == 0);
            #pragma unroll
            for (int mt = 0; mt < 2; ++mt)
                #pragma unroll
                for (int nt = 0; nt < 4; ++nt) {
                    float* d = acc[mt][nt];
                    float v0 = d[0] + bx[nt], v1 = d[1] + by[nt];
                    float v2 = d[2] + bx[nt], v3 = d[3] + by[nt];
                    v0 = v0 >= 0.f ? v0 : 0.2f * v0;
                    v1 = v1 >= 0.f ? v1 : 0.2f * v1;
                    v2 = v2 >= 0.f ? v2 : 0.2f * v2;
                    v3 = v3 >= 0.f ? v3 : 0.2f * v3;
                    float u0 = fmaxf(v0, __shfl_xor_sync(0xffffffffu, v0, 4));
                    float u1 = fmaxf(v1, __shfl_xor_sync(0xffffffffu, v1, 4));
                    float u2 = fmaxf(v2, __shfl_xor_sync(0xffffffffu, v2, 4));
                    float u3 = fmaxf(v3, __shfl_xor_sync(0xffffffffu, v3, 4));
                    if (storer) {
                        const int o0 = wn + nt * 8 + (l & 3) * 2;
                        const int jl = (wm + mt * 16 + r2) >> 1;   // 0..31
                        *(float2*)&stagef[jl * STAGE_STRIDE + o0] = make_float2(u0, u1);
                        *(float2*)&stagef[(jl + 4) * STAGE_STRIDE + o0] = make_float2(u2, u3);
                    }
                }
            __syncthreads();   // STS (buf^1) + stage complete

            // ---- 5. coalesced store: 32 rows x 128 floats ----
            const int jbase = tile << 5;
            #pragma unroll
            for (int k = 0; k < 4; ++k) {
                int idx = tid + k * THREADS;
                int row = idx >> 5, c4 = idx & 31;
                if (jbase + row < Lout) {
                    float4 v = *(const float4*)&stagef[row * STAGE_STRIDE + c4 * 4];
                    *(float4*)&Yout[(size_t)(jbase + row) * CCH + c4 * 4] = v;
                }
            }
            __syncthreads();   // stage free before next epilogue
            cur ^= 1;
        }

        grid_barrier();        // level complete chip-wide
        Xcur = Yout;
        L = Lout;
    }
}

// ---------------------------------------------------------------------------
extern "C" void kernel_launch(void* const* d_in, const int* in_sizes, int n_in,
                              void* d_out, int out_size) {
    const float* x     = (const float*)d_in[0];
    const float* depth = (const float*)d_in[1];
    const float* W     = (const float*)d_in[2];
    const float* b     = (const float*)d_in[3];
    const int*   perm  = (const int*)d_in[4];
    float* out = (float*)d_out;

    int N = in_sizes[0] / CCH;
    int nlev = 0;
    { int L = N; while (L > 1) { L = (L - 1) / 2; nlev++; } }

    cudaFuncSetAttribute((const void*)persistent_kernel,
                         cudaFuncAttributeMaxDynamicSharedMemorySize, SM_TOT);

    precompute_kernel<<<GRIDP, 256>>>(W, b, depth, nlev);

    float *bufA, *bufB;
    cudaGetSymbolAddress((void**)&bufA, g_bufA);
    cudaGetSymbolAddress((void**)&bufB, g_bufB);

    persistent_kernel<<<GRIDP, THREADS, SM_TOT>>>(x, perm, bufA, bufB, out, N);
}